// round 2
// baseline (speedup 1.0000x reference)
#include <cuda_runtime.h>
#include <cstdint>
#include <cstddef>

#define TT 64
#define BB 64
#define HH 1024
#define EE 512
#define VV 32000
#define VPAD 32768
#define NSTEP 63
#define NROWS (NSTEP*BB)   // 4032
#define GEMM_R 8           // rows per logits CTA
#define GEMM_CTAS (NROWS/GEMM_R)  // 504

// ---------------- device scratch (statics: allocation-free) ----------------
__device__ float g_xT[NSTEP*EE*BB];          // [t][e][b]  8.25MB
__device__ float g_h0[2][HH*BB];             // ping-pong, [k][b]
__device__ float g_h1[2][HH*BB];
__device__ float g_c0[HH*BB];
__device__ float g_c1[HH*BB];
__device__ float g_outs[(size_t)NSTEP*BB*HH];        // [t][b][k] 16.5MB
__device__ float g_WoutT[(size_t)HH*VPAD];           // [k][v]    134MB
__device__ float g_nll[NROWS];

// ---------------- packed f32x2 helpers ----------------
union F2 { unsigned long long u; float2 f; };

__device__ __forceinline__ unsigned long long fma2(unsigned long long a,
                                                   unsigned long long b,
                                                   unsigned long long c) {
    unsigned long long d;
    asm("fma.rn.f32x2 %0, %1, %2, %3;" : "=l"(d) : "l"(a), "l"(b), "l"(c));
    return d;
}
__device__ __forceinline__ unsigned long long dup2(float x) {
    F2 t; t.f.x = x; t.f.y = x; return t.u;
}
__device__ __forceinline__ float sigm(float x) {
    return 1.0f / (1.0f + __expf(-x));
}

// ---------------- embedding: x[t][e][b] = emb[tok]*(tok!=0) ----------------
__global__ void embed_kernel(const int* __restrict__ tok,
                             const float* __restrict__ emb) {
    int idx = blockIdx.x * 256 + threadIdx.x;
    if (idx >= NSTEP * EE * BB) return;
    int b = idx & 63;
    int e = (idx >> 6) & 511;
    int t = idx >> 15;
    int tk = tok[t * BB + b];
    g_xT[idx] = (tk == 0) ? 0.0f : emb[(size_t)tk * EE + e];
}

// ---------------- init h/c (transpose [l][b][k] -> [k][b]) ----------------
__global__ void init_kernel(const float* __restrict__ hid,
                            const float* __restrict__ cel) {
    int idx = blockIdx.x * 256 + threadIdx.x;   // k*64+b
    if (idx >= HH * BB) return;
    int b = idx & 63;
    int k = idx >> 6;
    g_h0[0][idx] = hid[(size_t)b * HH + k];
    g_h1[0][idx] = hid[(size_t)BB * HH + (size_t)b * HH + k];
    g_c0[idx]    = cel[(size_t)b * HH + k];
    g_c1[idx]    = cel[(size_t)BB * HH + (size_t)b * HH + k];
}

// ---------------- W_out transpose: WoutT[k][v] = W_out[v][k] ----------------
__global__ void transpose_wout(const float* __restrict__ W) {
    __shared__ float tile[32][33];
    int v0 = blockIdx.x * 32, k0 = blockIdx.y * 32;
    int tx = threadIdx.x, ty = threadIdx.y;
    for (int i = ty; i < 32; i += 8)
        tile[i][tx] = W[(size_t)(v0 + i) * HH + k0 + tx];
    __syncthreads();
    for (int i = ty; i < 32; i += 8)
        g_WoutT[(size_t)(k0 + i) * VPAD + v0 + tx] = tile[tx][i];
}

// ---------------- LSTM step (one layer) ----------------
// thread = (j, 4 consecutive b). gates packed over b-pairs via f32x2.
__device__ __forceinline__ void accum_pass(F2 acc[4][2],
                                           const float* __restrict__ A,
                                           const float* __restrict__ W,
                                           int K, int j, int b0) {
    for (int k = 0; k < K; k += 4) {
        float4 w[4];
        #pragma unroll
        for (int g = 0; g < 4; g++)
            w[g] = *(const float4*)(W + (size_t)(g * HH + j) * K + k);
        #pragma unroll
        for (int kk = 0; kk < 4; kk++) {
            float4 av = *(const float4*)(A + (k + kk) * BB + b0);
            F2 a01, a23;
            a01.f.x = av.x; a01.f.y = av.y;
            a23.f.x = av.z; a23.f.y = av.w;
            #pragma unroll
            for (int g = 0; g < 4; g++) {
                float wv = (kk == 0) ? w[g].x : (kk == 1) ? w[g].y
                         : (kk == 2) ? w[g].z : w[g].w;
                unsigned long long wd = dup2(wv);
                acc[g][0].u = fma2(wd, a01.u, acc[g][0].u);
                acc[g][1].u = fma2(wd, a23.u, acc[g][1].u);
            }
        }
    }
}

__global__ __launch_bounds__(128) void lstm_step(int t, int layer,
        const float* __restrict__ Wih, const float* __restrict__ Whh,
        const float* __restrict__ bih, const float* __restrict__ bhh) {
    int p = t & 1;
    const float *A1, *A2;
    float *hOut, *cBuf;
    int K1;
    if (layer == 0) {
        A1 = g_xT + (size_t)t * EE * BB; A2 = g_h0[p];
        hOut = g_h0[p ^ 1]; cBuf = g_c0; K1 = EE;
    } else {
        A1 = g_h0[p ^ 1]; A2 = g_h1[p];
        hOut = g_h1[p ^ 1]; cBuf = g_c1; K1 = HH;
    }

    int tid = threadIdx.x;
    int b0 = (tid & 15) * 4;
    int j  = blockIdx.x * 8 + (tid >> 4);

    F2 acc[4][2];
    #pragma unroll
    for (int g = 0; g < 4; g++) {
        float bias = bih[g * HH + j] + bhh[g * HH + j];
        acc[g][0].f.x = bias; acc[g][0].f.y = bias;
        acc[g][1] = acc[g][0];
    }

    accum_pass(acc, A1, Wih, K1, j, b0);
    accum_pass(acc, A2, Whh, HH, j, b0);

    float gv[4][4];   // [gate][b-lane]
    #pragma unroll
    for (int g = 0; g < 4; g++) {
        gv[g][0] = acc[g][0].f.x; gv[g][1] = acc[g][0].f.y;
        gv[g][2] = acc[g][1].f.x; gv[g][3] = acc[g][1].f.y;
    }
    #pragma unroll
    for (int i = 0; i < 4; i++) {
        int b = b0 + i;
        size_t idx = (size_t)j * BB + b;
        float I = sigm(gv[0][i]);
        float F = sigm(gv[1][i]);
        float G = tanhf(gv[2][i]);
        float O = sigm(gv[3][i]);
        float cn = F * cBuf[idx] + I * G;
        float hn = O * tanhf(cn);
        cBuf[idx] = cn;
        hOut[idx] = hn;
        if (layer == 1)
            g_outs[((size_t)t * BB + b) * HH + j] = hn;
    }
}

// ---------------- fused logits GEMM + online softmax/argmax ----------------
// CTA = 8 rows. Each thread: 4 vocab cols per 1024-v chunk, all 8 rows.
// Running (max, sumexp, argmax) per row per thread across the vocab loop.
__global__ __launch_bounds__(256) void logits_fused(const int* __restrict__ tok,
                                                    const float* __restrict__ bout,
                                                    float* __restrict__ d_out) {
    __shared__ float sh[GEMM_R * HH];   // sh[k*8 + ri], 32KB
    __shared__ float rm[256];
    __shared__ float rs[256];
    __shared__ int   ra[256];
    __shared__ float s_tgt[GEMM_R];

    int row0 = blockIdx.x * GEMM_R;
    int tid = threadIdx.x;

    for (int k = tid; k < HH; k += 256) {
        #pragma unroll
        for (int ri = 0; ri < GEMM_R; ri++)
            sh[k * GEMM_R + ri] = g_outs[(size_t)(row0 + ri) * HH + k];
    }

    // target indices for the 8 rows
    int tgt[GEMM_R];
    #pragma unroll
    for (int ri = 0; ri < GEMM_R; ri++) {
        int r = row0 + ri;
        tgt[ri] = tok[((r >> 6) + 1) * BB + (r & 63)];
    }
    __syncthreads();

    float m[GEMM_R], s[GEMM_R];
    int   arg[GEMM_R];
    #pragma unroll
    for (int ri = 0; ri < GEMM_R; ri++) {
        m[ri] = -__int_as_float(0x7f800000);
        s[ri] = 0.0f;
        arg[ri] = 0;
    }

    for (int vb = 0; vb < VV; vb += 1024) {
        int v = vb + tid * 4;
        if (v >= VV) continue;     // only last chunk, uniform-per-warp

        F2 acc[GEMM_R / 2][4];
        float4 bv = *(const float4*)(bout + v);
        #pragma unroll
        for (int rp = 0; rp < GEMM_R / 2; rp++) {
            acc[rp][0].u = dup2(bv.x);
            acc[rp][1].u = dup2(bv.y);
            acc[rp][2].u = dup2(bv.z);
            acc[rp][3].u = dup2(bv.w);
        }

        const float* wp = g_WoutT + v;
        for (int k = 0; k < HH; k++) {
            float4 w = *(const float4*)(wp + (size_t)k * VPAD);
            unsigned long long wd[4] = {dup2(w.x), dup2(w.y), dup2(w.z), dup2(w.w)};
            const ulonglong2* hp = (const ulonglong2*)(sh + k * GEMM_R);
            #pragma unroll
            for (int q = 0; q < GEMM_R / 4; q++) {
                ulonglong2 h2 = hp[q];
                #pragma unroll
                for (int vi = 0; vi < 4; vi++) {
                    acc[2 * q][vi].u     = fma2(h2.x, wd[vi], acc[2 * q][vi].u);
                    acc[2 * q + 1][vi].u = fma2(h2.y, wd[vi], acc[2 * q + 1][vi].u);
                }
            }
        }

        // online state update for the 4 v values x 8 rows
        #pragma unroll
        for (int rp = 0; rp < GEMM_R / 2; rp++) {
            #pragma unroll
            for (int half = 0; half < 2; half++) {
                int ri = 2 * rp + half;
                #pragma unroll
                for (int vi = 0; vi < 4; vi++) {
                    float l = half ? acc[rp][vi].f.y : acc[rp][vi].f.x;
                    int vv = v + vi;
                    if (vv == tgt[ri]) s_tgt[ri] = l;
                    if (l > m[ri]) {
                        s[ri] = s[ri] * __expf(m[ri] - l) + 1.0f;
                        m[ri] = l; arg[ri] = vv;
                    } else {
                        s[ri] += __expf(l - m[ri]);
                    }
                }
            }
        }
    }

    // block reduce, one row at a time
    for (int ri = 0; ri < GEMM_R; ri++) {
        __syncthreads();
        rm[tid] = m[ri]; rs[tid] = s[ri]; ra[tid] = arg[ri];
        __syncthreads();
        for (int st = 128; st > 0; st >>= 1) {
            if (tid < st) {
                float m1 = rm[tid], s1 = rs[tid]; int a1 = ra[tid];
                float m2 = rm[tid + st], s2 = rs[tid + st]; int a2 = ra[tid + st];
                if (m2 > m1 || (m2 == m1 && a2 < a1)) {
                    rm[tid] = m2; rs[tid] = s2 + s1 * __expf(m1 - m2); ra[tid] = a2;
                } else {
                    rs[tid] = s1 + s2 * __expf(m2 - m1);
                }
            }
            __syncthreads();
        }
        if (tid == 0) {
            int r = row0 + ri;
            int t = r >> 6, b = r & 63;
            float lse = rm[0] + __logf(rs[0]);
            g_nll[r] = lse - s_tgt[ri];
            d_out[1 + (size_t)(t + 1) * BB + b] = (float)ra[0];
        }
    }
}

// ---------------- final loss + first prediction row ----------------
__global__ void loss_kernel(const int* __restrict__ tok, float* __restrict__ d_out) {
    __shared__ float sh[64];
    int tid = threadIdx.x;  // 64
    float ce = 0.0f;
    if (tid < NSTEP) {
        float sum = 0.0f, cnt = 0.0f;
        for (int b = 0; b < BB; b++) {
            int tg = tok[(tid + 1) * BB + b];
            if (tg != 1) { sum += g_nll[tid * BB + b]; cnt += 1.0f; }
        }
        ce = sum / fmaxf(cnt, 1.0f);
    }
    sh[tid] = ce;
    __syncthreads();
    for (int st = 32; st > 0; st >>= 1) {
        if (tid < st) sh[tid] += sh[tid + st];
        __syncthreads();
    }
    if (tid == 0) d_out[0] = sh[0] / (float)TT;
    d_out[1 + tid] = 2.0f;   // result row 0 = 2
}

// ---------------- launch ----------------
extern "C" void kernel_launch(void* const* d_in, const int* in_sizes, int n_in,
                              void* d_out, int out_size) {
    const int*   tok = (const int*)d_in[0];
    const float* hid = (const float*)d_in[3];
    const float* cel = (const float*)d_in[4];
    // index 6 is either max_length (size 1) or emb, depending on harness scalar handling
    int base = (in_sizes[6] == 1) ? 7 : 6;
    const float* emb  = (const float*)d_in[base];
    const float* Wih0 = (const float*)d_in[base + 1];
    const float* Whh0 = (const float*)d_in[base + 2];
    const float* bih0 = (const float*)d_in[base + 3];
    const float* bhh0 = (const float*)d_in[base + 4];
    const float* Wih1 = (const float*)d_in[base + 5];
    const float* Whh1 = (const float*)d_in[base + 6];
    const float* bih1 = (const float*)d_in[base + 7];
    const float* bhh1 = (const float*)d_in[base + 8];
    const float* Wout = (const float*)d_in[base + 9];
    const float* bout = (const float*)d_in[base + 10];
    float* out = (float*)d_out;

    embed_kernel<<<(NSTEP * EE * BB + 255) / 256, 256>>>(tok, emb);
    init_kernel<<<(HH * BB + 255) / 256, 256>>>(hid, cel);
    transpose_wout<<<dim3(VV / 32, HH / 32), dim3(32, 8)>>>(Wout);

    for (int t = 0; t < NSTEP; t++) {
        lstm_step<<<HH / 8, 128>>>(t, 0, Wih0, Whh0, bih0, bhh0);
        lstm_step<<<HH / 8, 128>>>(t, 1, Wih1, Whh1, bih1, bhh1);
    }

    logits_fused<<<GEMM_CTAS, 256>>>(tok, bout, out);
    loss_kernel<<<1, 64>>>(tok, out);
}

// round 3
// speedup vs baseline: 1.0029x; 1.0029x over previous
#include <cuda_runtime.h>
#include <cstdint>
#include <cstddef>

#define TT 64
#define BB 64
#define HH 1024
#define EE 512
#define VV 32000
#define VPAD 32768
#define NSTEP 63
#define NROWS (NSTEP*BB)   // 4032
#define GEMM_R 8           // rows per logits CTA
#define GEMM_CTAS (NROWS/GEMM_R)  // 504

// ---------------- device scratch (statics: allocation-free) ----------------
__device__ float g_xT[NSTEP*EE*BB];          // [t][e][b]  8.25MB
__device__ float g_h0[2][HH*BB];             // ping-pong, [k][b]
__device__ float g_h1[2][HH*BB];
__device__ float g_c0[HH*BB];
__device__ float g_c1[HH*BB];
__device__ float g_outs[(size_t)NSTEP*BB*HH];        // [t][b][k] 16.5MB
__device__ float g_WoutT[(size_t)HH*VPAD];           // [k][v]    134MB
__device__ float g_nll[NROWS];

// ---------------- packed f32x2 helpers ----------------
union F2 { unsigned long long u; float2 f; };

__device__ __forceinline__ unsigned long long fma2(unsigned long long a,
                                                   unsigned long long b,
                                                   unsigned long long c) {
    unsigned long long d;
    asm("fma.rn.f32x2 %0, %1, %2, %3;" : "=l"(d) : "l"(a), "l"(b), "l"(c));
    return d;
}
__device__ __forceinline__ unsigned long long dup2(float x) {
    F2 t; t.f.x = x; t.f.y = x; return t.u;
}
__device__ __forceinline__ float sigm(float x) {
    return 1.0f / (1.0f + __expf(-x));
}

// ---------------- embedding: x[t][e][b] = emb[tok]*(tok!=0) ----------------
__global__ void embed_kernel(const int* __restrict__ tok,
                             const float* __restrict__ emb) {
    int idx = blockIdx.x * 256 + threadIdx.x;
    if (idx >= NSTEP * EE * BB) return;
    int b = idx & 63;
    int e = (idx >> 6) & 511;
    int t = idx >> 15;
    int tk = tok[t * BB + b];
    g_xT[idx] = (tk == 0) ? 0.0f : emb[(size_t)tk * EE + e];
}

// ---------------- init h/c (transpose [l][b][k] -> [k][b]) ----------------
__global__ void init_kernel(const float* __restrict__ hid,
                            const float* __restrict__ cel) {
    int idx = blockIdx.x * 256 + threadIdx.x;   // k*64+b
    if (idx >= HH * BB) return;
    int b = idx & 63;
    int k = idx >> 6;
    g_h0[0][idx] = hid[(size_t)b * HH + k];
    g_h1[0][idx] = hid[(size_t)BB * HH + (size_t)b * HH + k];
    g_c0[idx]    = cel[(size_t)b * HH + k];
    g_c1[idx]    = cel[(size_t)BB * HH + (size_t)b * HH + k];
}

// ---------------- W_out transpose: WoutT[k][v] = W_out[v][k] ----------------
__global__ void transpose_wout(const float* __restrict__ W) {
    __shared__ float tile[32][33];
    int v0 = blockIdx.x * 32, k0 = blockIdx.y * 32;
    int tx = threadIdx.x, ty = threadIdx.y;
    for (int i = ty; i < 32; i += 8)
        tile[i][tx] = W[(size_t)(v0 + i) * HH + k0 + tx];
    __syncthreads();
    for (int i = ty; i < 32; i += 8)
        g_WoutT[(size_t)(k0 + i) * VPAD + v0 + tx] = tile[tx][i];
}

// ---------------- LSTM step (one layer) ----------------
// thread = (j, 4 consecutive b). gates packed over b-pairs via f32x2.
__device__ __forceinline__ void accum_pass(F2 acc[4][2],
                                           const float* __restrict__ A,
                                           const float* __restrict__ W,
                                           int K, int j, int b0) {
    for (int k = 0; k < K; k += 4) {
        float4 w[4];
        #pragma unroll
        for (int g = 0; g < 4; g++)
            w[g] = *(const float4*)(W + (size_t)(g * HH + j) * K + k);
        #pragma unroll
        for (int kk = 0; kk < 4; kk++) {
            float4 av = *(const float4*)(A + (k + kk) * BB + b0);
            F2 a01, a23;
            a01.f.x = av.x; a01.f.y = av.y;
            a23.f.x = av.z; a23.f.y = av.w;
            #pragma unroll
            for (int g = 0; g < 4; g++) {
                float wv = (kk == 0) ? w[g].x : (kk == 1) ? w[g].y
                         : (kk == 2) ? w[g].z : w[g].w;
                unsigned long long wd = dup2(wv);
                acc[g][0].u = fma2(wd, a01.u, acc[g][0].u);
                acc[g][1].u = fma2(wd, a23.u, acc[g][1].u);
            }
        }
    }
}

__global__ __launch_bounds__(128) void lstm_step(int t, int layer,
        const float* __restrict__ Wih, const float* __restrict__ Whh,
        const float* __restrict__ bih, const float* __restrict__ bhh) {
    int p = t & 1;
    const float *A1, *A2;
    float *hOut, *cBuf;
    int K1;
    if (layer == 0) {
        A1 = g_xT + (size_t)t * EE * BB; A2 = g_h0[p];
        hOut = g_h0[p ^ 1]; cBuf = g_c0; K1 = EE;
    } else {
        A1 = g_h0[p ^ 1]; A2 = g_h1[p];
        hOut = g_h1[p ^ 1]; cBuf = g_c1; K1 = HH;
    }

    int tid = threadIdx.x;
    int b0 = (tid & 15) * 4;
    int j  = blockIdx.x * 8 + (tid >> 4);

    F2 acc[4][2];
    #pragma unroll
    for (int g = 0; g < 4; g++) {
        float bias = bih[g * HH + j] + bhh[g * HH + j];
        acc[g][0].f.x = bias; acc[g][0].f.y = bias;
        acc[g][1] = acc[g][0];
    }

    accum_pass(acc, A1, Wih, K1, j, b0);
    accum_pass(acc, A2, Whh, HH, j, b0);

    float gv[4][4];   // [gate][b-lane]
    #pragma unroll
    for (int g = 0; g < 4; g++) {
        gv[g][0] = acc[g][0].f.x; gv[g][1] = acc[g][0].f.y;
        gv[g][2] = acc[g][1].f.x; gv[g][3] = acc[g][1].f.y;
    }
    #pragma unroll
    for (int i = 0; i < 4; i++) {
        int b = b0 + i;
        size_t idx = (size_t)j * BB + b;
        float I = sigm(gv[0][i]);
        float F = sigm(gv[1][i]);
        float G = tanhf(gv[2][i]);
        float O = sigm(gv[3][i]);
        float cn = F * cBuf[idx] + I * G;
        float hn = O * tanhf(cn);
        cBuf[idx] = cn;
        hOut[idx] = hn;
        if (layer == 1)
            g_outs[((size_t)t * BB + b) * HH + j] = hn;
    }
}

// ---------------- fused logits GEMM + online softmax/argmax ----------------
// CTA = 8 rows. Each thread: 4 vocab cols per 1024-v chunk, all 8 rows.
// Running (max, sumexp, argmax) per row per thread across the vocab loop.
__global__ __launch_bounds__(256) void logits_fused(const int* __restrict__ tok,
                                                    const float* __restrict__ bout,
                                                    float* __restrict__ d_out) {
    __shared__ float sh[GEMM_R * HH];   // sh[k*8 + ri], 32KB
    __shared__ float rm[256];
    __shared__ float rs[256];
    __shared__ int   ra[256];
    __shared__ float s_tgt[GEMM_R];

    int row0 = blockIdx.x * GEMM_R;
    int tid = threadIdx.x;

    for (int k = tid; k < HH; k += 256) {
        #pragma unroll
        for (int ri = 0; ri < GEMM_R; ri++)
            sh[k * GEMM_R + ri] = g_outs[(size_t)(row0 + ri) * HH + k];
    }

    // target indices for the 8 rows
    int tgt[GEMM_R];
    #pragma unroll
    for (int ri = 0; ri < GEMM_R; ri++) {
        int r = row0 + ri;
        tgt[ri] = tok[((r >> 6) + 1) * BB + (r & 63)];
    }
    __syncthreads();

    float m[GEMM_R], s[GEMM_R];
    int   arg[GEMM_R];
    #pragma unroll
    for (int ri = 0; ri < GEMM_R; ri++) {
        m[ri] = -__int_as_float(0x7f800000);
        s[ri] = 0.0f;
        arg[ri] = 0;
    }

    for (int vb = 0; vb < VV; vb += 1024) {
        int v = vb + tid * 4;
        if (v >= VV) continue;     // only last chunk, uniform-per-warp

        F2 acc[GEMM_R / 2][4];
        float4 bv = *(const float4*)(bout + v);
        #pragma unroll
        for (int rp = 0; rp < GEMM_R / 2; rp++) {
            acc[rp][0].u = dup2(bv.x);
            acc[rp][1].u = dup2(bv.y);
            acc[rp][2].u = dup2(bv.z);
            acc[rp][3].u = dup2(bv.w);
        }

        const float* wp = g_WoutT + v;
        for (int k = 0; k < HH; k++) {
            float4 w = *(const float4*)(wp + (size_t)k * VPAD);
            unsigned long long wd[4] = {dup2(w.x), dup2(w.y), dup2(w.z), dup2(w.w)};
            const ulonglong2* hp = (const ulonglong2*)(sh + k * GEMM_R);
            #pragma unroll
            for (int q = 0; q < GEMM_R / 4; q++) {
                ulonglong2 h2 = hp[q];
                #pragma unroll
                for (int vi = 0; vi < 4; vi++) {
                    acc[2 * q][vi].u     = fma2(h2.x, wd[vi], acc[2 * q][vi].u);
                    acc[2 * q + 1][vi].u = fma2(h2.y, wd[vi], acc[2 * q + 1][vi].u);
                }
            }
        }

        // online state update for the 4 v values x 8 rows
        #pragma unroll
        for (int rp = 0; rp < GEMM_R / 2; rp++) {
            #pragma unroll
            for (int half = 0; half < 2; half++) {
                int ri = 2 * rp + half;
                #pragma unroll
                for (int vi = 0; vi < 4; vi++) {
                    float l = half ? acc[rp][vi].f.y : acc[rp][vi].f.x;
                    int vv = v + vi;
                    if (vv == tgt[ri]) s_tgt[ri] = l;
                    if (l > m[ri]) {
                        s[ri] = s[ri] * __expf(m[ri] - l) + 1.0f;
                        m[ri] = l; arg[ri] = vv;
                    } else {
                        s[ri] += __expf(l - m[ri]);
                    }
                }
            }
        }
    }

    // block reduce, one row at a time
    for (int ri = 0; ri < GEMM_R; ri++) {
        __syncthreads();
        rm[tid] = m[ri]; rs[tid] = s[ri]; ra[tid] = arg[ri];
        __syncthreads();
        for (int st = 128; st > 0; st >>= 1) {
            if (tid < st) {
                float m1 = rm[tid], s1 = rs[tid]; int a1 = ra[tid];
                float m2 = rm[tid + st], s2 = rs[tid + st]; int a2 = ra[tid + st];
                if (m2 > m1 || (m2 == m1 && a2 < a1)) {
                    rm[tid] = m2; rs[tid] = s2 + s1 * __expf(m1 - m2); ra[tid] = a2;
                } else {
                    rs[tid] = s1 + s2 * __expf(m2 - m1);
                }
            }
            __syncthreads();
        }
        if (tid == 0) {
            int r = row0 + ri;
            int t = r >> 6, b = r & 63;
            float lse = rm[0] + __logf(rs[0]);
            g_nll[r] = lse - s_tgt[ri];
            d_out[1 + (size_t)(t + 1) * BB + b] = (float)ra[0];
        }
    }
}

// ---------------- final loss + first prediction row ----------------
__global__ void loss_kernel(const int* __restrict__ tok, float* __restrict__ d_out) {
    __shared__ float sh[64];
    int tid = threadIdx.x;  // 64
    float ce = 0.0f;
    if (tid < NSTEP) {
        float sum = 0.0f, cnt = 0.0f;
        for (int b = 0; b < BB; b++) {
            int tg = tok[(tid + 1) * BB + b];
            if (tg != 1) { sum += g_nll[tid * BB + b]; cnt += 1.0f; }
        }
        ce = sum / fmaxf(cnt, 1.0f);
    }
    sh[tid] = ce;
    __syncthreads();
    for (int st = 32; st > 0; st >>= 1) {
        if (tid < st) sh[tid] += sh[tid + st];
        __syncthreads();
    }
    if (tid == 0) d_out[0] = sh[0] / (float)TT;
    d_out[1 + tid] = 2.0f;   // result row 0 = 2
}

// ---------------- launch ----------------
extern "C" void kernel_launch(void* const* d_in, const int* in_sizes, int n_in,
                              void* d_out, int out_size) {
    const int*   tok = (const int*)d_in[0];
    const float* hid = (const float*)d_in[3];
    const float* cel = (const float*)d_in[4];
    // index 6 is either max_length (size 1) or emb, depending on harness scalar handling
    int base = (in_sizes[6] == 1) ? 7 : 6;
    const float* emb  = (const float*)d_in[base];
    const float* Wih0 = (const float*)d_in[base + 1];
    const float* Whh0 = (const float*)d_in[base + 2];
    const float* bih0 = (const float*)d_in[base + 3];
    const float* bhh0 = (const float*)d_in[base + 4];
    const float* Wih1 = (const float*)d_in[base + 5];
    const float* Whh1 = (const float*)d_in[base + 6];
    const float* bih1 = (const float*)d_in[base + 7];
    const float* bhh1 = (const float*)d_in[base + 8];
    const float* Wout = (const float*)d_in[base + 9];
    const float* bout = (const float*)d_in[base + 10];
    float* out = (float*)d_out;

    embed_kernel<<<(NSTEP * EE * BB + 255) / 256, 256>>>(tok, emb);
    init_kernel<<<(HH * BB + 255) / 256, 256>>>(hid, cel);
    transpose_wout<<<dim3(VV / 32, HH / 32), dim3(32, 8)>>>(Wout);

    for (int t = 0; t < NSTEP; t++) {
        lstm_step<<<HH / 8, 128>>>(t, 0, Wih0, Whh0, bih0, bhh0);
        lstm_step<<<HH / 8, 128>>>(t, 1, Wih1, Whh1, bih1, bhh1);
    }

    logits_fused<<<GEMM_CTAS, 256>>>(tok, bout, out);
    loss_kernel<<<1, 64>>>(tok, out);
}